// round 2
// baseline (speedup 1.0000x reference)
#include <cuda_runtime.h>
#include <cstdint>

// Problem constants (fixed by dataset)
#define NMAX 100000
#define DIM  64

// Scratch: aggregation buffer agg[N][64]
__device__ __align__(16) float g_agg[NMAX * DIM];

// ---------------------------------------------------------------------------
// Kernel 1: zero the agg buffer (float4 stores)
// ---------------------------------------------------------------------------
__global__ void zero_kernel(int n4) {
    int i = blockIdx.x * blockDim.x + threadIdx.x;
    if (i < n4) ((float4*)g_agg)[i] = make_float4(0.f, 0.f, 0.f, 0.f);
}

// ---------------------------------------------------------------------------
// Kernel 2: edge scatter. 16 threads per edge, one float4 lane each.
// Vector RED (no-return atomic) to minimize L2 atomic ops.
// NOTE: row/col are int32 (JAX demotes int64 without x64 mode).
// ---------------------------------------------------------------------------
__device__ __forceinline__ void red_add_f32x4(float* addr, float4 v) {
    asm volatile("red.global.add.v4.f32 [%0], {%1, %2, %3, %4};"
                 :: "l"(addr), "f"(v.x), "f"(v.y), "f"(v.z), "f"(v.w)
                 : "memory");
}

__global__ void scatter_kernel(const float* __restrict__ x,
                               const int* __restrict__ row,
                               const int* __restrict__ col,
                               int E, int N) {
    int gid = blockIdx.x * blockDim.x + threadIdx.x;
    int e = gid >> 4;
    if (e >= E) return;
    int j = gid & 15;
    int r = __ldg(row + e);
    int c = __ldg(col + e);
    // Defensive: OOB indices become a correctness error, not a crash.
    if ((unsigned)r >= (unsigned)N || (unsigned)c >= (unsigned)N) return;
    float4 v = __ldg((const float4*)x + r * 16 + j);
    red_add_f32x4(g_agg + c * DIM + j * 4, v);
}

// ---------------------------------------------------------------------------
// Kernel 3: fused GEMM  out = relu([x | agg/norm] @ [root_W^T; rel_W^T] + b)
// M = N nodes, K = 128, Ncols = 64.
// Block: 256 threads, tile = 64 nodes x 64 outputs, 4x4 register tile/thread.
// Shared: Ws [128][WS_STRIDE] (W transposed, padded), As [64][AS_STRIDE].
// ---------------------------------------------------------------------------
#define WS_STRIDE 68   // 128-bit aligned rows, conflict-free LDS.128 reads
#define AS_STRIDE 132  // 128 + 4 pad, 16B-aligned
#define SMEM_BYTES ((128 * WS_STRIDE + 64 * AS_STRIDE) * 4)

__global__ void compute_kernel(const float* __restrict__ x,
                               const float* __restrict__ adj_norm,
                               const float* __restrict__ root_W,
                               const float* __restrict__ root_b,
                               const float* __restrict__ rel_W,
                               float* __restrict__ out,
                               int N) {
    extern __shared__ float smem[];
    float* Ws = smem;                       // [128][WS_STRIDE]: Ws[k][d]
    float* As = smem + 128 * WS_STRIDE;     // [64][AS_STRIDE]:  As[n][k]

    int tid = threadIdx.x;

    // Load both weight matrices, transposed: Ws[k][d] = W[d][k]
    // k in [0,64)  -> root_W  (multiplies x part of A)
    // k in [64,128)-> rel_W   (multiplies agg part of A)
    for (int idx = tid; idx < 2 * 64 * 64; idx += 256) {
        int m   = idx >> 12;       // 0 = root, 1 = rel
        int rem = idx & 4095;
        int d   = rem >> 6;
        int kk  = rem & 63;        // coalesced along kk
        const float* src = m ? rel_W : root_W;
        Ws[(m * 64 + kk) * WS_STRIDE + d] = src[d * 64 + kk];
    }
    __syncthreads();

    int n0 = blockIdx.x * 64;

    // Load A tile: As[n][0:64] = x[g], As[n][64:128] = agg[g] / adj_norm[g]
    for (int idx = tid; idx < 64 * 32; idx += 256) {
        int n = idx >> 5;
        int j = idx & 31;
        int g = n0 + n;
        float4 v = make_float4(0.f, 0.f, 0.f, 0.f);
        if (g < N) {
            if (j < 16) {
                v = __ldg((const float4*)x + g * 16 + j);
            } else {
                v = *((const float4*)g_agg + g * 16 + (j - 16));
                float inv = 1.0f / __ldg(adj_norm + g);
                v.x *= inv; v.y *= inv; v.z *= inv; v.w *= inv;
            }
        }
        *(float4*)(As + n * AS_STRIDE + j * 4) = v;
    }
    __syncthreads();

    int tx = tid & 15;   // output-dim group: d = 4*tx + [0..3]
    int ty = tid >> 4;   // node group:       n = n0 + 4*ty + [0..3]

    float acc[4][4];
    #pragma unroll
    for (int i = 0; i < 4; i++)
        #pragma unroll
        for (int j = 0; j < 4; j++)
            acc[i][j] = __ldg(root_b + tx * 4 + j);

    #pragma unroll 4
    for (int k = 0; k < 128; k += 4) {
        float4 a[4];
        #pragma unroll
        for (int i = 0; i < 4; i++)
            a[i] = *(float4*)(As + (ty * 4 + i) * AS_STRIDE + k);
        float4 w[4];
        #pragma unroll
        for (int j = 0; j < 4; j++)
            w[j] = *(float4*)(Ws + (k + j) * WS_STRIDE + tx * 4);
        #pragma unroll
        for (int i = 0; i < 4; i++) {
            acc[i][0] += a[i].x * w[0].x + a[i].y * w[1].x + a[i].z * w[2].x + a[i].w * w[3].x;
            acc[i][1] += a[i].x * w[0].y + a[i].y * w[1].y + a[i].z * w[2].y + a[i].w * w[3].y;
            acc[i][2] += a[i].x * w[0].z + a[i].y * w[1].z + a[i].z * w[2].z + a[i].w * w[3].z;
            acc[i][3] += a[i].x * w[0].w + a[i].y * w[1].w + a[i].z * w[2].w + a[i].w * w[3].w;
        }
    }

    #pragma unroll
    for (int i = 0; i < 4; i++) {
        int g = n0 + ty * 4 + i;
        if (g < N) {
            float4 o;
            o.x = fmaxf(acc[i][0], 0.f);
            o.y = fmaxf(acc[i][1], 0.f);
            o.z = fmaxf(acc[i][2], 0.f);
            o.w = fmaxf(acc[i][3], 0.f);
            *((float4*)out + g * 16 + tx) = o;
        }
    }
}

// ---------------------------------------------------------------------------
// Launch
// Inputs (metadata order): x f32[N*64], row i32[E], col i32[E], batch i32[N],
//                          adj_norm f32[N], root_W f32[64*64], root_b f32[64],
//                          rel_W f32[64*64]. Output f32[N*64].
// ---------------------------------------------------------------------------
extern "C" void kernel_launch(void* const* d_in, const int* in_sizes, int n_in,
                              void* d_out, int out_size) {
    const float* x        = (const float*)d_in[0];
    const int*   row      = (const int*)d_in[1];
    const int*   col      = (const int*)d_in[2];
    const float* adj_norm = (const float*)d_in[4];
    const float* root_W   = (const float*)d_in[5];
    const float* root_b   = (const float*)d_in[6];
    const float* rel_W    = (const float*)d_in[7];
    float*       out      = (float*)d_out;

    int E = in_sizes[1];
    int N = in_sizes[4];

    // 1) zero agg
    int n4 = N * 16;
    zero_kernel<<<(n4 + 255) / 256, 256>>>(n4);

    // 2) edge scatter (16 threads/edge)
    long long work = (long long)E * 16;
    int sblocks = (int)((work + 255) / 256);
    scatter_kernel<<<sblocks, 256>>>(x, row, col, E, N);

    // 3) fused GEMM + bias + relu
    cudaFuncSetAttribute(compute_kernel,
                         cudaFuncAttributeMaxDynamicSharedMemorySize, SMEM_BYTES);
    compute_kernel<<<(N + 63) / 64, 256, SMEM_BYTES>>>(
        x, adj_norm, root_W, root_b, rel_W, out, N);
}

// round 3
// speedup vs baseline: 1.0512x; 1.0512x over previous
#include <cuda_runtime.h>
#include <cstdint>

// Problem constants (fixed by dataset)
#define NMAX 100000
#define EMAX 1600000
#define DIM  64

// CSR scratch (device globals; no allocation allowed)
__device__ int g_deg[NMAX];
__device__ int g_off[NMAX];
__device__ int g_cur[NMAX];
__device__ int g_srcs[EMAX];
__device__ int g_base;

// ---------------------------------------------------------------------------
// K1: init degree counters + base
// ---------------------------------------------------------------------------
__global__ void init_kernel(int N) {
    int i = blockIdx.x * blockDim.x + threadIdx.x;
    if (i < N) g_deg[i] = 0;
    if (i == 0) g_base = 0;
}

// ---------------------------------------------------------------------------
// K2: histogram of destination degrees
// ---------------------------------------------------------------------------
__global__ void hist_kernel(const int* __restrict__ col, int E, int N) {
    int e = blockIdx.x * blockDim.x + threadIdx.x;
    if (e < E) {
        int c = __ldg(col + e);
        if ((unsigned)c < (unsigned)N) atomicAdd(&g_deg[c], 1);
    }
}

// ---------------------------------------------------------------------------
// K3: chunked exclusive scan. Each block scans 256 degrees, grabs a
// contiguous region via one atomicAdd on g_base. Offsets are valid
// (disjoint, contiguous per node) even though chunk order is arbitrary.
// ---------------------------------------------------------------------------
__global__ void scan_kernel(int N) {
    __shared__ int warp_part[8];
    __shared__ int s_base;
    int i = blockIdx.x * 256 + threadIdx.x;
    int v = (i < N) ? g_deg[i] : 0;
    int lane = threadIdx.x & 31, wid = threadIdx.x >> 5;

    int s = v;
    #pragma unroll
    for (int d = 1; d < 32; d <<= 1) {
        int t = __shfl_up_sync(0xffffffffu, s, d);
        if (lane >= d) s += t;
    }
    if (lane == 31) warp_part[wid] = s;
    __syncthreads();
    if (wid == 0) {
        int p = (lane < 8) ? warp_part[lane] : 0;
        #pragma unroll
        for (int d = 1; d < 8; d <<= 1) {
            int t = __shfl_up_sync(0xffffffffu, p, d);
            if (lane >= d) p += t;
        }
        if (lane < 8) warp_part[lane] = p;
    }
    __syncthreads();
    int incl = s + (wid > 0 ? warp_part[wid - 1] : 0);
    if (threadIdx.x == 255) s_base = atomicAdd(&g_base, incl);
    __syncthreads();
    int excl = incl - v + s_base;
    if (i < N) { g_off[i] = excl; g_cur[i] = excl; }
}

// ---------------------------------------------------------------------------
// K4: place source indices into CSR buckets
// ---------------------------------------------------------------------------
__global__ void place_kernel(const int* __restrict__ row,
                             const int* __restrict__ col, int E, int N) {
    int e = blockIdx.x * blockDim.x + threadIdx.x;
    if (e < E) {
        int c = __ldg(col + e);
        int r = __ldg(row + e);
        if ((unsigned)c >= (unsigned)N || (unsigned)r >= (unsigned)N) return;
        int pos = atomicAdd(&g_cur[c], 1);
        g_srcs[pos] = r;
    }
}

// ---------------------------------------------------------------------------
// K5: fused CSR gather-sum + GEMM + bias + relu
// out = relu([x | csr_sum(x)/norm] @ [root_W^T; rel_W^T] + b)
// Block: 256 threads, tile = 64 nodes x 64 outputs.
// Gather: 4 threads per node, each owns 4 float4 lanes (64B) of the row.
// ---------------------------------------------------------------------------
#define WS_STRIDE 68
#define AS_STRIDE 132
#define SMEM_BYTES ((128 * WS_STRIDE + 64 * AS_STRIDE) * 4)

__global__ void fused_kernel(const float* __restrict__ x,
                             const float* __restrict__ adj_norm,
                             const float* __restrict__ root_W,
                             const float* __restrict__ root_b,
                             const float* __restrict__ rel_W,
                             float* __restrict__ out,
                             int N) {
    extern __shared__ float smem[];
    float* Ws = smem;                       // [128][WS_STRIDE]: Ws[k][d]
    float* As = smem + 128 * WS_STRIDE;     // [64][AS_STRIDE]:  As[n][k]

    int tid = threadIdx.x;
    int n0 = blockIdx.x * 64;

    // Weights, transposed: Ws[k][d]; k<64 -> root_W, k>=64 -> rel_W
    for (int idx = tid; idx < 2 * 64 * 64; idx += 256) {
        int m   = idx >> 12;
        int rem = idx & 4095;
        int d   = rem >> 6;
        int kk  = rem & 63;
        const float* src = m ? rel_W : root_W;
        Ws[(m * 64 + kk) * WS_STRIDE + d] = src[d * 64 + kk];
    }

    // CSR gather: node = tid>>2, quad = tid&3 handles float4 slots [quad*4, quad*4+4)
    {
        int n_local = tid >> 2;
        int quad    = tid & 3;
        int g       = n0 + n_local;

        float4 a[4];
        float4 xr[4];
        #pragma unroll
        for (int u = 0; u < 4; u++) {
            a[u]  = make_float4(0.f, 0.f, 0.f, 0.f);
            xr[u] = make_float4(0.f, 0.f, 0.f, 0.f);
        }

        if (g < N) {
            const float4* xp = (const float4*)x + (size_t)g * 16 + quad * 4;
            #pragma unroll
            for (int u = 0; u < 4; u++) xr[u] = __ldg(xp + u);

            int deg = g_deg[g];
            int off = g_off[g];
            for (int i = 0; i < deg; i++) {
                int s = g_srcs[off + i];   // 4 lanes of a node share this (L1 bcast)
                const float4* sp = (const float4*)x + (size_t)s * 16 + quad * 4;
                #pragma unroll
                for (int u = 0; u < 4; u++) {
                    float4 v = __ldg(sp + u);
                    a[u].x += v.x; a[u].y += v.y; a[u].z += v.z; a[u].w += v.w;
                }
            }
            float inv = 1.0f / __ldg(adj_norm + g);
            #pragma unroll
            for (int u = 0; u < 4; u++) {
                a[u].x *= inv; a[u].y *= inv; a[u].z *= inv; a[u].w *= inv;
            }
        }

        float* rowp = As + n_local * AS_STRIDE;
        #pragma unroll
        for (int u = 0; u < 4; u++) {
            *(float4*)(rowp + (quad * 4 + u) * 4)      = xr[u];   // k in [0,64)
            *(float4*)(rowp + 64 + (quad * 4 + u) * 4) = a[u];    // k in [64,128)
        }
    }
    __syncthreads();

    // GEMM: 4x4 register tile per thread
    int tx = tid & 15;   // output-dim group: d = 4*tx + [0..3]
    int ty = tid >> 4;   // node group:       n = n0 + 4*ty + [0..3]

    float acc[4][4];
    #pragma unroll
    for (int i = 0; i < 4; i++)
        #pragma unroll
        for (int j = 0; j < 4; j++)
            acc[i][j] = __ldg(root_b + tx * 4 + j);

    #pragma unroll 4
    for (int k = 0; k < 128; k += 4) {
        float4 a[4];
        #pragma unroll
        for (int i = 0; i < 4; i++)
            a[i] = *(float4*)(As + (ty * 4 + i) * AS_STRIDE + k);
        float4 w[4];
        #pragma unroll
        for (int j = 0; j < 4; j++)
            w[j] = *(float4*)(Ws + (k + j) * WS_STRIDE + tx * 4);
        #pragma unroll
        for (int i = 0; i < 4; i++) {
            acc[i][0] += a[i].x * w[0].x + a[i].y * w[1].x + a[i].z * w[2].x + a[i].w * w[3].x;
            acc[i][1] += a[i].x * w[0].y + a[i].y * w[1].y + a[i].z * w[2].y + a[i].w * w[3].y;
            acc[i][2] += a[i].x * w[0].z + a[i].y * w[1].z + a[i].z * w[2].z + a[i].w * w[3].z;
            acc[i][3] += a[i].x * w[0].w + a[i].y * w[1].w + a[i].z * w[2].w + a[i].w * w[3].w;
        }
    }

    #pragma unroll
    for (int i = 0; i < 4; i++) {
        int g = n0 + ty * 4 + i;
        if (g < N) {
            float4 o;
            o.x = fmaxf(acc[i][0], 0.f);
            o.y = fmaxf(acc[i][1], 0.f);
            o.z = fmaxf(acc[i][2], 0.f);
            o.w = fmaxf(acc[i][3], 0.f);
            *((float4*)out + (size_t)g * 16 + tx) = o;
        }
    }
}

// ---------------------------------------------------------------------------
// Launch.
// Inputs: x f32[N*64], row i32[E], col i32[E], batch i32[N],
//         adj_norm f32[N], root_W f32[64*64], root_b f32[64], rel_W f32[64*64]
// ---------------------------------------------------------------------------
extern "C" void kernel_launch(void* const* d_in, const int* in_sizes, int n_in,
                              void* d_out, int out_size) {
    const float* x        = (const float*)d_in[0];
    const int*   row      = (const int*)d_in[1];
    const int*   col      = (const int*)d_in[2];
    const float* adj_norm = (const float*)d_in[4];
    const float* root_W   = (const float*)d_in[5];
    const float* root_b   = (const float*)d_in[6];
    const float* rel_W    = (const float*)d_in[7];
    float*       out      = (float*)d_out;

    int E = in_sizes[1];
    int N = in_sizes[4];

    int nblk = (N + 255) / 256;
    int eblk = (E + 255) / 256;

    init_kernel<<<nblk, 256>>>(N);
    hist_kernel<<<eblk, 256>>>(col, E, N);
    scan_kernel<<<nblk, 256>>>(N);
    place_kernel<<<eblk, 256>>>(row, col, E, N);

    cudaFuncSetAttribute(fused_kernel,
                         cudaFuncAttributeMaxDynamicSharedMemorySize, SMEM_BYTES);
    fused_kernel<<<(N + 63) / 64, 256, SMEM_BYTES>>>(
        x, adj_norm, root_W, root_b, rel_W, out, N);
}

// round 4
// speedup vs baseline: 1.0954x; 1.0420x over previous
#include <cuda_runtime.h>
#include <cstdint>

#define NMAX 100000
#define EMAX 1600000
#define DIM  64

// Scratch
__device__ int g_deg[NMAX];
__device__ int g_off[NMAX];
__device__ int g_cur[NMAX];
__device__ int g_srcs[EMAX];
__device__ int g_base;
__device__ __align__(16) float g_agg[NMAX * DIM];   // normalized agg

// ---------------------------------------------------------------------------
// K1: init
// ---------------------------------------------------------------------------
__global__ void init_kernel(int N) {
    int i = blockIdx.x * blockDim.x + threadIdx.x;
    if (i < N) g_deg[i] = 0;
    if (i == 0) g_base = 0;
}

// ---------------------------------------------------------------------------
// K2: degree histogram, 4 edges/thread for ILP
// ---------------------------------------------------------------------------
__global__ void hist_kernel(const int* __restrict__ col, int E, int N) {
    int t = blockIdx.x * blockDim.x + threadIdx.x;
    int e0 = t * 4;
    if (e0 + 3 < E) {
        int4 c = __ldg((const int4*)(col + e0));
        atomicAdd(&g_deg[c.x], 1);
        atomicAdd(&g_deg[c.y], 1);
        atomicAdd(&g_deg[c.z], 1);
        atomicAdd(&g_deg[c.w], 1);
    } else {
        for (int e = e0; e < E; e++) {
            int c = __ldg(col + e);
            if ((unsigned)c < (unsigned)N) atomicAdd(&g_deg[c], 1);
        }
    }
}

// ---------------------------------------------------------------------------
// K3: chunked exclusive scan (256/block, one atomic per block)
// ---------------------------------------------------------------------------
__global__ void scan_kernel(int N) {
    __shared__ int warp_part[8];
    __shared__ int s_base;
    int i = blockIdx.x * 256 + threadIdx.x;
    int v = (i < N) ? g_deg[i] : 0;
    int lane = threadIdx.x & 31, wid = threadIdx.x >> 5;

    int s = v;
    #pragma unroll
    for (int d = 1; d < 32; d <<= 1) {
        int t = __shfl_up_sync(0xffffffffu, s, d);
        if (lane >= d) s += t;
    }
    if (lane == 31) warp_part[wid] = s;
    __syncthreads();
    if (wid == 0) {
        int p = (lane < 8) ? warp_part[lane] : 0;
        #pragma unroll
        for (int d = 1; d < 8; d <<= 1) {
            int t = __shfl_up_sync(0xffffffffu, p, d);
            if (lane >= d) p += t;
        }
        if (lane < 8) warp_part[lane] = p;
    }
    __syncthreads();
    int incl = s + (wid > 0 ? warp_part[wid - 1] : 0);
    if (threadIdx.x == 255) s_base = atomicAdd(&g_base, incl);
    __syncthreads();
    int excl = incl - v + s_base;
    if (i < N) { g_off[i] = excl; g_cur[i] = excl; }
}

// ---------------------------------------------------------------------------
// K4: place sources into CSR buckets, 4 edges/thread for ILP
// ---------------------------------------------------------------------------
__global__ void place_kernel(const int* __restrict__ row,
                             const int* __restrict__ col, int E, int N) {
    int t = blockIdx.x * blockDim.x + threadIdx.x;
    int e0 = t * 4;
    if (e0 + 3 < E) {
        int4 c = __ldg((const int4*)(col + e0));
        int4 r = __ldg((const int4*)(row + e0));
        int p0 = atomicAdd(&g_cur[c.x], 1);
        int p1 = atomicAdd(&g_cur[c.y], 1);
        int p2 = atomicAdd(&g_cur[c.z], 1);
        int p3 = atomicAdd(&g_cur[c.w], 1);
        g_srcs[p0] = r.x;
        g_srcs[p1] = r.y;
        g_srcs[p2] = r.z;
        g_srcs[p3] = r.w;
    } else {
        for (int e = e0; e < E; e++) {
            int c = __ldg(col + e);
            int r = __ldg(row + e);
            if ((unsigned)c >= (unsigned)N || (unsigned)r >= (unsigned)N) continue;
            int pos = atomicAdd(&g_cur[c], 1);
            g_srcs[pos] = r;
        }
    }
}

// ---------------------------------------------------------------------------
// K5: CSR gather-sum, normalized. 16 lanes per node (one float4 each),
// 2 nodes per warp, edge loop unrolled x4. Stores g_agg = sum(x[srcs])/norm.
// No block-level coupling -> imbalance is only pairwise within a warp.
// ---------------------------------------------------------------------------
__global__ void gather_kernel(const float* __restrict__ x,
                              const float* __restrict__ adj_norm,
                              int N) {
    int tid    = threadIdx.x;
    int lane   = tid & 31;
    int warp   = tid >> 5;
    int node_h = lane >> 4;          // which of the warp's 2 nodes
    int l16    = lane & 15;          // float4 slot within the row
    int g = blockIdx.x * 16 + warp * 2 + node_h;
    if (g >= N) return;

    int deg = g_deg[g];
    int off = g_off[g];
    const float4* x4 = (const float4*)x;

    float4 a0 = make_float4(0.f, 0.f, 0.f, 0.f);
    float4 a1 = make_float4(0.f, 0.f, 0.f, 0.f);
    float4 a2 = make_float4(0.f, 0.f, 0.f, 0.f);
    float4 a3 = make_float4(0.f, 0.f, 0.f, 0.f);

    int i = 0;
    for (; i + 4 <= deg; i += 4) {
        int s0 = __ldg(g_srcs + off + i);
        int s1 = __ldg(g_srcs + off + i + 1);
        int s2 = __ldg(g_srcs + off + i + 2);
        int s3 = __ldg(g_srcs + off + i + 3);
        float4 v0 = __ldg(x4 + (size_t)s0 * 16 + l16);
        float4 v1 = __ldg(x4 + (size_t)s1 * 16 + l16);
        float4 v2 = __ldg(x4 + (size_t)s2 * 16 + l16);
        float4 v3 = __ldg(x4 + (size_t)s3 * 16 + l16);
        a0.x += v0.x; a0.y += v0.y; a0.z += v0.z; a0.w += v0.w;
        a1.x += v1.x; a1.y += v1.y; a1.z += v1.z; a1.w += v1.w;
        a2.x += v2.x; a2.y += v2.y; a2.z += v2.z; a2.w += v2.w;
        a3.x += v3.x; a3.y += v3.y; a3.z += v3.z; a3.w += v3.w;
    }
    for (; i < deg; i++) {
        int s = __ldg(g_srcs + off + i);
        float4 v = __ldg(x4 + (size_t)s * 16 + l16);
        a0.x += v.x; a0.y += v.y; a0.z += v.z; a0.w += v.w;
    }

    float inv = 1.0f / __ldg(adj_norm + g);
    float4 a;
    a.x = (a0.x + a1.x + a2.x + a3.x) * inv;
    a.y = (a0.y + a1.y + a2.y + a3.y) * inv;
    a.z = (a0.z + a1.z + a2.z + a3.z) * inv;
    a.w = (a0.w + a1.w + a2.w + a3.w) * inv;
    *((float4*)g_agg + (size_t)g * 16 + l16) = a;
}

// ---------------------------------------------------------------------------
// K6: GEMM  out = relu([x | agg] @ [root_W^T; rel_W^T] + b)
// Block: 256 threads, tile = 64 nodes x 64 outputs, 4x4 register tile.
// ---------------------------------------------------------------------------
#define WS_STRIDE 68
#define AS_STRIDE 132
#define SMEM_BYTES ((128 * WS_STRIDE + 64 * AS_STRIDE) * 4)

__global__ void compute_kernel(const float* __restrict__ x,
                               const float* __restrict__ root_W,
                               const float* __restrict__ root_b,
                               const float* __restrict__ rel_W,
                               float* __restrict__ out,
                               int N) {
    extern __shared__ float smem[];
    float* Ws = smem;                       // [128][WS_STRIDE]
    float* As = smem + 128 * WS_STRIDE;     // [64][AS_STRIDE]

    int tid = threadIdx.x;
    int n0 = blockIdx.x * 64;

    for (int idx = tid; idx < 2 * 64 * 64; idx += 256) {
        int m   = idx >> 12;
        int rem = idx & 4095;
        int d   = rem >> 6;
        int kk  = rem & 63;
        const float* src = m ? rel_W : root_W;
        Ws[(m * 64 + kk) * WS_STRIDE + d] = src[d * 64 + kk];
    }

    for (int idx = tid; idx < 64 * 32; idx += 256) {
        int n = idx >> 5;
        int j = idx & 31;
        int g = n0 + n;
        float4 v = make_float4(0.f, 0.f, 0.f, 0.f);
        if (g < N) {
            if (j < 16) v = __ldg((const float4*)x + (size_t)g * 16 + j);
            else        v = *((const float4*)g_agg + (size_t)g * 16 + (j - 16));
        }
        *(float4*)(As + n * AS_STRIDE + j * 4) = v;
    }
    __syncthreads();

    int tx = tid & 15;
    int ty = tid >> 4;

    float acc[4][4];
    #pragma unroll
    for (int i = 0; i < 4; i++)
        #pragma unroll
        for (int j = 0; j < 4; j++)
            acc[i][j] = __ldg(root_b + tx * 4 + j);

    #pragma unroll 4
    for (int k = 0; k < 128; k += 4) {
        float4 a[4];
        #pragma unroll
        for (int i = 0; i < 4; i++)
            a[i] = *(float4*)(As + (ty * 4 + i) * AS_STRIDE + k);
        float4 w[4];
        #pragma unroll
        for (int j = 0; j < 4; j++)
            w[j] = *(float4*)(Ws + (k + j) * WS_STRIDE + tx * 4);
        #pragma unroll
        for (int i = 0; i < 4; i++) {
            acc[i][0] += a[i].x * w[0].x + a[i].y * w[1].x + a[i].z * w[2].x + a[i].w * w[3].x;
            acc[i][1] += a[i].x * w[0].y + a[i].y * w[1].y + a[i].z * w[2].y + a[i].w * w[3].y;
            acc[i][2] += a[i].x * w[0].z + a[i].y * w[1].z + a[i].z * w[2].z + a[i].w * w[3].z;
            acc[i][3] += a[i].x * w[0].w + a[i].y * w[1].w + a[i].z * w[2].w + a[i].w * w[3].w;
        }
    }

    #pragma unroll
    for (int i = 0; i < 4; i++) {
        int g = n0 + ty * 4 + i;
        if (g < N) {
            float4 o;
            o.x = fmaxf(acc[i][0], 0.f);
            o.y = fmaxf(acc[i][1], 0.f);
            o.z = fmaxf(acc[i][2], 0.f);
            o.w = fmaxf(acc[i][3], 0.f);
            *((float4*)out + (size_t)g * 16 + tx) = o;
        }
    }
}

// ---------------------------------------------------------------------------
// Launch
// ---------------------------------------------------------------------------
extern "C" void kernel_launch(void* const* d_in, const int* in_sizes, int n_in,
                              void* d_out, int out_size) {
    const float* x        = (const float*)d_in[0];
    const int*   row      = (const int*)d_in[1];
    const int*   col      = (const int*)d_in[2];
    const float* adj_norm = (const float*)d_in[4];
    const float* root_W   = (const float*)d_in[5];
    const float* root_b   = (const float*)d_in[6];
    const float* rel_W    = (const float*)d_in[7];
    float*       out      = (float*)d_out;

    int E = in_sizes[1];
    int N = in_sizes[4];

    int nblk  = (N + 255) / 256;
    int eblk4 = ((E + 3) / 4 + 255) / 256;

    init_kernel<<<nblk, 256>>>(N);
    hist_kernel<<<eblk4, 256>>>(col, E, N);
    scan_kernel<<<nblk, 256>>>(N);
    place_kernel<<<eblk4, 256>>>(row, col, E, N);
    gather_kernel<<<(N + 15) / 16, 256>>>(x, adj_norm, N);

    cudaFuncSetAttribute(compute_kernel,
                         cudaFuncAttributeMaxDynamicSharedMemorySize, SMEM_BYTES);
    compute_kernel<<<(N + 63) / 64, 256, SMEM_BYTES>>>(
        x, root_W, root_b, rel_W, out, N);
}